// round 1
// baseline (speedup 1.0000x reference)
#include <cuda_runtime.h>
#include <cstdint>

// Problem constants
#define BB 32
#define NN 512
#define CC 1024
#define HH 16
#define HD 64
#define SCALE 0.125f   // 64^-0.5

// Scratch: [B,H,N,HD] for q/k/v, [B,N,C] for attention output
__device__ float g_q[BB * HH * NN * HD];
__device__ float g_k[BB * HH * NN * HD];
__device__ float g_v[BB * HH * NN * HD];
__device__ float g_o[BB * NN * CC];

// ---------------------------------------------------------------------------
// Tiled SGEMM: C[M, Nout] = A[M,1024] * W[Nout,1024]^T
// BM=BN=128, BK=16, 256 threads, 8x8 micro-tile per thread.
// MODE 0: A = x, W = W_qkv (Nout=3072). Epilogue scatters into g_q/g_k/g_v
//         (q scaled by SCALE).
// MODE 1: A = g_o, W = W_proj (Nout=1024). Epilogue writes out + bias.
// ---------------------------------------------------------------------------
template <int MODE>
__global__ __launch_bounds__(256, 2)
void gemm128(const float* __restrict__ Ain, const float* __restrict__ Bw,
             const float* __restrict__ bias, float* __restrict__ out) {
    const int tileN = blockIdx.x * 128;
    const int tileM = blockIdx.y * 128;
    const float* A = (MODE == 1) ? g_o : Ain;

    __shared__ float As[16 * 128];
    __shared__ float Bs[16 * 128];

    const int tid = threadIdx.x;
    const int ty = tid >> 4;        // 0..15  (row group)
    const int tx = tid & 15;        // 0..15  (col group)
    const int r0 = tid >> 2;        // 0..63
    const int c0 = (tid & 3) << 2;  // 0,4,8,12

    const float* Ap0 = A + (size_t)(tileM + r0) * 1024 + c0;
    const float* Ap1 = Ap0 + (size_t)64 * 1024;
    const float* Bp0 = Bw + (size_t)(tileN + r0) * 1024 + c0;
    const float* Bp1 = Bp0 + (size_t)64 * 1024;

    float4 pa0 = *(const float4*)(Ap0);
    float4 pa1 = *(const float4*)(Ap1);
    float4 pb0 = *(const float4*)(Bp0);
    float4 pb1 = *(const float4*)(Bp1);

    float acc[8][8];
#pragma unroll
    for (int i = 0; i < 8; i++)
#pragma unroll
        for (int j = 0; j < 8; j++) acc[i][j] = 0.f;

#pragma unroll 1
    for (int t = 0; t < 64; t++) {
        // store current tile (transposed: As[k][m])
        As[(c0 + 0) * 128 + r0] = pa0.x;
        As[(c0 + 1) * 128 + r0] = pa0.y;
        As[(c0 + 2) * 128 + r0] = pa0.z;
        As[(c0 + 3) * 128 + r0] = pa0.w;
        As[(c0 + 0) * 128 + r0 + 64] = pa1.x;
        As[(c0 + 1) * 128 + r0 + 64] = pa1.y;
        As[(c0 + 2) * 128 + r0 + 64] = pa1.z;
        As[(c0 + 3) * 128 + r0 + 64] = pa1.w;
        Bs[(c0 + 0) * 128 + r0] = pb0.x;
        Bs[(c0 + 1) * 128 + r0] = pb0.y;
        Bs[(c0 + 2) * 128 + r0] = pb0.z;
        Bs[(c0 + 3) * 128 + r0] = pb0.w;
        Bs[(c0 + 0) * 128 + r0 + 64] = pb1.x;
        Bs[(c0 + 1) * 128 + r0 + 64] = pb1.y;
        Bs[(c0 + 2) * 128 + r0 + 64] = pb1.z;
        Bs[(c0 + 3) * 128 + r0 + 64] = pb1.w;
        __syncthreads();

        if (t < 63) {  // prefetch next K-tile into registers (hidden by compute)
            int off = (t + 1) * 16;
            pa0 = *(const float4*)(Ap0 + off);
            pa1 = *(const float4*)(Ap1 + off);
            pb0 = *(const float4*)(Bp0 + off);
            pb1 = *(const float4*)(Bp1 + off);
        }

#pragma unroll
        for (int kk = 0; kk < 16; kk++) {
            float4 a0 = *(const float4*)(As + kk * 128 + ty * 8);
            float4 a1 = *(const float4*)(As + kk * 128 + ty * 8 + 4);
            float4 b0 = *(const float4*)(Bs + kk * 128 + tx * 8);
            float4 b1 = *(const float4*)(Bs + kk * 128 + tx * 8 + 4);
            float av[8] = {a0.x, a0.y, a0.z, a0.w, a1.x, a1.y, a1.z, a1.w};
            float bv[8] = {b0.x, b0.y, b0.z, b0.w, b1.x, b1.y, b1.z, b1.w};
#pragma unroll
            for (int i = 0; i < 8; i++)
#pragma unroll
                for (int j = 0; j < 8; j++) acc[i][j] += av[i] * bv[j];
        }
        __syncthreads();
    }

    const int gm0 = tileM + ty * 8;
    const int gd0 = tileN + tx * 8;

    if (MODE == 0) {
        // scatter into q/k/v  [B,H,N,HD]; head index constant per thread
        const int which = gd0 >> 10;         // 0=q 1=k 2=v
        const int h = (gd0 >> 6) & (HH - 1); // head
        const int hd = gd0 & (HD - 1);       // contiguous 8 within head_dim
        float* dst = (which == 0) ? g_q : (which == 1) ? g_k : g_v;
        const float sc = (which == 0) ? SCALE : 1.0f;
#pragma unroll
        for (int i = 0; i < 8; i++) {
            int gm = gm0 + i;
            int b = gm >> 9;
            int n = gm & (NN - 1);
            size_t base = (((size_t)(b * HH + h) * NN) + n) * HD + hd;
            float4 w0 = make_float4(acc[i][0] * sc, acc[i][1] * sc,
                                    acc[i][2] * sc, acc[i][3] * sc);
            float4 w1 = make_float4(acc[i][4] * sc, acc[i][5] * sc,
                                    acc[i][6] * sc, acc[i][7] * sc);
            *(float4*)(dst + base) = w0;
            *(float4*)(dst + base + 4) = w1;
        }
    } else {
        float4 bi0 = *(const float4*)(bias + gd0);
        float4 bi1 = *(const float4*)(bias + gd0 + 4);
#pragma unroll
        for (int i = 0; i < 8; i++) {
            int gm = gm0 + i;
            float4 w0 = make_float4(acc[i][0] + bi0.x, acc[i][1] + bi0.y,
                                    acc[i][2] + bi0.z, acc[i][3] + bi0.w);
            float4 w1 = make_float4(acc[i][4] + bi1.x, acc[i][5] + bi1.y,
                                    acc[i][6] + bi1.z, acc[i][7] + bi1.w);
            *(float4*)(out + (size_t)gm * CC + gd0) = w0;
            *(float4*)(out + (size_t)gm * CC + gd0 + 4) = w1;
        }
    }
}

// ---------------------------------------------------------------------------
// Attention: one block per (b,h, 64-query tile). Full 64x512 score tile in
// smem, warp-per-row softmax, then P*V. Only the key-side mask term is added
// (the query-side term is constant per row -> cancels exactly in softmax).
// smem: s[64][516] + q[64][68] + kv[64][68] + mk[512] = 168960 B
// ---------------------------------------------------------------------------
#define S_LD 516
#define QK_LD 68
#define ATTN_SMEM ((64 * S_LD + 2 * 64 * QK_LD + 512) * 4)

__global__ __launch_bounds__(256, 1)
void attn_kernel(const float* __restrict__ mask) {
    extern __shared__ float sm[];
    float* s = sm;                       // 64 x 516
    float* qs = s + 64 * S_LD;           // 64 x 68
    float* kvs = qs + 64 * QK_LD;        // 64 x 68
    float* mk = kvs + 64 * QK_LD;        // 512

    const int bh = blockIdx.y;           // b*H + h
    const int b = bh >> 4;
    const int h = bh & (HH - 1);
    const int q0 = blockIdx.x * 64;
    const int tid = threadIdx.x;
    const int ty = tid >> 4;             // 0..15
    const int tx = tid & 15;             // 0..15

    const float* qg = g_q + (size_t)bh * NN * HD;
    const float* kg = g_k + (size_t)bh * NN * HD;
    const float* vg = g_v + (size_t)bh * NN * HD;

    for (int i = tid; i < NN; i += 256) mk[i] = mask[b * NN + i];

    // load Q tile (pre-scaled)
    for (int p = tid; p < 64 * 16; p += 256) {
        int r = p >> 4, c4 = (p & 15) << 2;
        *(float4*)(qs + r * QK_LD + c4) =
            *(const float4*)(qg + (size_t)(q0 + r) * HD + c4);
    }

    // ---- S = Q K^T + mask_key ----
    for (int kt = 0; kt < 8; kt++) {
        __syncthreads();
        for (int p = tid; p < 64 * 16; p += 256) {
            int r = p >> 4, c4 = (p & 15) << 2;
            *(float4*)(kvs + r * QK_LD + c4) =
                *(const float4*)(kg + (size_t)(kt * 64 + r) * HD + c4);
        }
        __syncthreads();

        float acc[4][4];
#pragma unroll
        for (int i = 0; i < 4; i++)
#pragma unroll
            for (int j = 0; j < 4; j++) acc[i][j] = 0.f;

#pragma unroll
        for (int kk = 0; kk < 64; kk += 4) {
            float a_[4][4], b_[4][4];
#pragma unroll
            for (int i = 0; i < 4; i++) {
                float4 t = *(const float4*)(qs + (ty * 4 + i) * QK_LD + kk);
                a_[i][0] = t.x; a_[i][1] = t.y; a_[i][2] = t.z; a_[i][3] = t.w;
            }
#pragma unroll
            for (int j = 0; j < 4; j++) {
                float4 t = *(const float4*)(kvs + (tx * 4 + j) * QK_LD + kk);
                b_[j][0] = t.x; b_[j][1] = t.y; b_[j][2] = t.z; b_[j][3] = t.w;
            }
#pragma unroll
            for (int i = 0; i < 4; i++)
#pragma unroll
                for (int j = 0; j < 4; j++)
#pragma unroll
                    for (int u = 0; u < 4; u++) acc[i][j] += a_[i][u] * b_[j][u];
        }
#pragma unroll
        for (int i = 0; i < 4; i++)
#pragma unroll
            for (int j = 0; j < 4; j++)
                s[(ty * 4 + i) * S_LD + kt * 64 + tx * 4 + j] =
                    acc[i][j] + mk[kt * 64 + tx * 4 + j];
    }
    __syncthreads();

    // ---- softmax: one warp per row ----
    const int warp = tid >> 5, lane = tid & 31;
    for (int r = warp; r < 64; r += 8) {
        float* row = s + r * S_LD;
        float m = -1e30f;
        for (int j = lane; j < NN; j += 32) m = fmaxf(m, row[j]);
#pragma unroll
        for (int o = 16; o > 0; o >>= 1)
            m = fmaxf(m, __shfl_xor_sync(0xffffffffu, m, o));
        float l = 0.f;
        for (int j = lane; j < NN; j += 32) {
            float e = __expf(row[j] - m);
            row[j] = e;
            l += e;
        }
#pragma unroll
        for (int o = 16; o > 0; o >>= 1) l += __shfl_xor_sync(0xffffffffu, l, o);
        float inv = 1.0f / l;
        for (int j = lane; j < NN; j += 32) row[j] *= inv;
    }

    // ---- O = P V ----
    float oacc[4][4];
#pragma unroll
    for (int i = 0; i < 4; i++)
#pragma unroll
        for (int j = 0; j < 4; j++) oacc[i][j] = 0.f;

    for (int vt = 0; vt < 8; vt++) {
        __syncthreads();
        for (int p = tid; p < 64 * 16; p += 256) {
            int r = p >> 4, c4 = (p & 15) << 2;
            *(float4*)(kvs + r * QK_LD + c4) =
                *(const float4*)(vg + (size_t)(vt * 64 + r) * HD + c4);
        }
        __syncthreads();

#pragma unroll
        for (int kk = 0; kk < 64; kk += 4) {
            float a_[4][4], b_[4][4];
#pragma unroll
            for (int i = 0; i < 4; i++) {
                float4 t = *(const float4*)(s + (ty * 4 + i) * S_LD + vt * 64 + kk);
                a_[i][0] = t.x; a_[i][1] = t.y; a_[i][2] = t.z; a_[i][3] = t.w;
            }
#pragma unroll
            for (int u = 0; u < 4; u++) {
                float4 t = *(const float4*)(kvs + (kk + u) * QK_LD + tx * 4);
                b_[u][0] = t.x; b_[u][1] = t.y; b_[u][2] = t.z; b_[u][3] = t.w;
            }
#pragma unroll
            for (int i = 0; i < 4; i++)
#pragma unroll
                for (int j = 0; j < 4; j++)
#pragma unroll
                    for (int u = 0; u < 4; u++) oacc[i][j] += a_[i][u] * b_[u][j];
        }
    }

    // write [B,N,C] so the projection GEMM reads contiguous rows
    float* og = g_o + ((size_t)b * NN + q0) * CC + h * HD;
#pragma unroll
    for (int i = 0; i < 4; i++) {
        float4 w = make_float4(oacc[i][0], oacc[i][1], oacc[i][2], oacc[i][3]);
        *(float4*)(og + (size_t)(ty * 4 + i) * CC + tx * 4) = w;
    }
}

// ---------------------------------------------------------------------------
extern "C" void kernel_launch(void* const* d_in, const int* in_sizes, int n_in,
                              void* d_out, int out_size) {
    const float* x = (const float*)d_in[0];      // [B,N,C]
    const float* mask = (const float*)d_in[1];   // [B,N]
    const float* W_qkv = (const float*)d_in[2];  // [3C,C]
    const float* W_proj = (const float*)d_in[3]; // [C,C]
    const float* b_proj = (const float*)d_in[4]; // [C]
    float* out = (float*)d_out;                  // [B,N,C]

    static bool attr_set = false;
    if (!attr_set) {
        cudaFuncSetAttribute(attn_kernel,
                             cudaFuncAttributeMaxDynamicSharedMemorySize,
                             ATTN_SMEM);
        attr_set = true;
    }

    // 1) QKV projection + scatter (q scaled)
    gemm128<0><<<dim3(3 * CC / 128, BB * NN / 128), 256>>>(x, W_qkv, nullptr,
                                                           nullptr);
    // 2) attention
    attn_kernel<<<dim3(NN / 64, BB * HH), 256, ATTN_SMEM>>>(mask);
    // 3) output projection + bias
    gemm128<1><<<dim3(CC / 128, BB * NN / 128), 256>>>(nullptr, W_proj, b_proj,
                                                       out);
}

// round 2
// speedup vs baseline: 3.0991x; 3.0991x over previous
#include <cuda_runtime.h>
#include <cstdint>

#define BB 32
#define NN 512
#define CC 1024
#define HH 16
#define HD 64
#define SCALE 0.125f
#define MTOT (BB * NN)   // 16384

// tf32-bit scratch (uint32 holds tf32-rounded fp32 bit pattern)
__device__ uint32_t g_xt[MTOT * CC];
__device__ uint32_t g_wqkvt[3 * CC * CC];
__device__ uint32_t g_wpt[CC * CC];
__device__ uint32_t g_qt[BB * HH * NN * HD];
__device__ uint32_t g_kt[BB * HH * NN * HD];
__device__ uint32_t g_vt[BB * HH * NN * HD];
__device__ uint32_t g_ot[MTOT * CC];

__device__ __forceinline__ uint32_t f2t(float x) {
    uint32_t y;
    asm("cvt.rna.tf32.f32 %0, %1;" : "=r"(y) : "f"(x));
    return y;
}

__device__ __forceinline__ void mma8(float* d, const uint32_t* a, const uint32_t* b) {
    asm volatile(
        "mma.sync.aligned.m16n8k8.row.col.f32.tf32.tf32.f32 "
        "{%0,%1,%2,%3}, {%4,%5,%6,%7}, {%8,%9}, {%0,%1,%2,%3};"
        : "+f"(d[0]), "+f"(d[1]), "+f"(d[2]), "+f"(d[3])
        : "r"(a[0]), "r"(a[1]), "r"(a[2]), "r"(a[3]), "r"(b[0]), "r"(b[1]));
}

// ---------------------------------------------------------------------------
// Elementwise fp32 -> tf32-bits conversion (DST selects device buffer)
// ---------------------------------------------------------------------------
template <int DST>
__global__ void cvt_kernel(const float* __restrict__ src) {
    uint32_t* dst = (DST == 0) ? g_xt : (DST == 1) ? g_wqkvt : g_wpt;
    int i = (blockIdx.x * 256 + threadIdx.x) * 4;
    float4 v = *(const float4*)(src + i);
    *(uint4*)(dst + i) = make_uint4(f2t(v.x), f2t(v.y), f2t(v.z), f2t(v.w));
}

// ---------------------------------------------------------------------------
// tf32 tensor-core GEMM: C[M,Nout] = A[M,1024] * W[Nout,1024]^T
// BM=BN=128, BK=16, 128 threads (4 warps), warp tile 64x64 (im=4, jn=8).
// MODE 0: A=g_xt, W=g_wqkvt -> scatter tf32 bits into g_qt/g_kt/g_vt
// MODE 1: A=g_ot, W=g_wpt   -> fp32 out + bias
// ---------------------------------------------------------------------------
#define SA 20   // smem row stride (16 + 4): (20*g + t) distinct mod 32

template <int MODE>
__global__ __launch_bounds__(128, 2)
void gemm_tf32(const float* __restrict__ bias, float* __restrict__ out) {
    const uint32_t* A = (MODE == 0) ? g_xt : g_ot;
    const uint32_t* W = (MODE == 0) ? g_wqkvt : g_wpt;
    const int tileN = blockIdx.x * 128;
    const int tileM = blockIdx.y * 128;

    __shared__ uint32_t As[128 * SA];
    __shared__ uint32_t Bs[128 * SA];

    const int tid = threadIdx.x, warp = tid >> 5, lane = tid & 31;
    const int g = lane >> 2, t = lane & 3;
    const int wm = (warp & 1) * 64, wn = (warp >> 1) * 64;
    const int lr = tid >> 2, lc = (tid & 3) << 2;

    const uint32_t* Ap = A + (size_t)(tileM + lr) * CC + lc;
    const uint32_t* Wp = W + (size_t)(tileN + lr) * CC + lc;

    uint4 pa[4], pb[4];
#pragma unroll
    for (int i = 0; i < 4; i++) {
        pa[i] = *(const uint4*)(Ap + (size_t)(i * 32) * CC);
        pb[i] = *(const uint4*)(Wp + (size_t)(i * 32) * CC);
    }

    float acc[4][8][4];
#pragma unroll
    for (int im = 0; im < 4; im++)
#pragma unroll
        for (int jn = 0; jn < 8; jn++)
#pragma unroll
            for (int c = 0; c < 4; c++) acc[im][jn][c] = 0.f;

#pragma unroll 1
    for (int kt = 0; kt < 64; kt++) {
#pragma unroll
        for (int i = 0; i < 4; i++) {
            *(uint4*)(As + (lr + i * 32) * SA + lc) = pa[i];
            *(uint4*)(Bs + (lr + i * 32) * SA + lc) = pb[i];
        }
        __syncthreads();
        if (kt < 63) {
            int off = (kt + 1) * 16;
#pragma unroll
            for (int i = 0; i < 4; i++) {
                pa[i] = *(const uint4*)(Ap + (size_t)(i * 32) * CC + off);
                pb[i] = *(const uint4*)(Wp + (size_t)(i * 32) * CC + off);
            }
        }
#pragma unroll
        for (int ks = 0; ks < 2; ks++) {
            const int k0 = ks * 8;
            uint32_t af[4][4], bf[8][2];
#pragma unroll
            for (int im = 0; im < 4; im++) {
                int rb = wm + im * 16;
                af[im][0] = As[(rb + g) * SA + k0 + t];
                af[im][1] = As[(rb + g + 8) * SA + k0 + t];
                af[im][2] = As[(rb + g) * SA + k0 + t + 4];
                af[im][3] = As[(rb + g + 8) * SA + k0 + t + 4];
            }
#pragma unroll
            for (int jn = 0; jn < 8; jn++) {
                int cb = wn + jn * 8;
                bf[jn][0] = Bs[(cb + g) * SA + k0 + t];
                bf[jn][1] = Bs[(cb + g) * SA + k0 + t + 4];
            }
#pragma unroll
            for (int im = 0; im < 4; im++)
#pragma unroll
                for (int jn = 0; jn < 8; jn++) mma8(acc[im][jn], af[im], bf[jn]);
        }
        __syncthreads();
    }

    if (MODE == 0) {
        const int colbase = tileN + wn;           // multiple of 64
        const int which = colbase >> 10;          // 0=q 1=k 2=v
        const int h = (colbase >> 6) & (HH - 1);
        uint32_t* dst = (which == 0) ? g_qt : (which == 1) ? g_kt : g_vt;
        const float sc = (which == 0) ? SCALE : 1.0f;
#pragma unroll
        for (int im = 0; im < 4; im++) {
            int r0 = tileM + wm + im * 16 + g;
#pragma unroll
            for (int rr = 0; rr < 2; rr++) {
                int row = r0 + rr * 8;
                int b = row >> 9, n = row & (NN - 1);
                uint32_t* dp = dst + ((size_t)(b * HH + h) * NN + n) * HD;
#pragma unroll
                for (int jn = 0; jn < 8; jn++) {
                    int hd = jn * 8 + 2 * t;
                    uint2 v = make_uint2(f2t(acc[im][jn][rr * 2 + 0] * sc),
                                         f2t(acc[im][jn][rr * 2 + 1] * sc));
                    *(uint2*)(dp + hd) = v;
                }
            }
        }
    } else {
#pragma unroll
        for (int jn = 0; jn < 8; jn++) {
            int col = tileN + wn + jn * 8 + 2 * t;
            float2 bi = *(const float2*)(bias + col);
#pragma unroll
            for (int im = 0; im < 4; im++) {
                int r0 = tileM + wm + im * 16 + g;
                float2 v0 = make_float2(acc[im][jn][0] + bi.x, acc[im][jn][1] + bi.y);
                float2 v1 = make_float2(acc[im][jn][2] + bi.x, acc[im][jn][3] + bi.y);
                *(float2*)(out + (size_t)r0 * CC + col) = v0;
                *(float2*)(out + (size_t)(r0 + 8) * CC + col) = v1;
            }
        }
    }
}

// ---------------------------------------------------------------------------
// Attention: block per (b,h, 64-query tile). tf32 mma for QK^T and PV,
// fp32 softmax in smem, P converted to tf32 bits in-place during normalize.
// Only the key-side mask term is added (query-side cancels in softmax).
// ---------------------------------------------------------------------------
#define SLD 516   // 512 + 4 : (516*g + t) % 32 == (4g+t) -> conflict-free
#define QLD 68    // 64 + 4
#define VLD 72    // 64 + 8 : (72*t + g) % 32 == (8t+g) -> conflict-free
#define S_OFF 0
#define Q_OFF (64 * SLD)
#define K_OFF (Q_OFF + 64 * QLD)
#define V_OFF (K_OFF + 64 * QLD)
#define MK_OFF (V_OFF + 64 * VLD)
#define ATTN_WORDS (MK_OFF + 512)
#define ATTN_SMEM (ATTN_WORDS * 4)

__global__ __launch_bounds__(256, 1)
void attn_tf32(const float* __restrict__ mask) {
    extern __shared__ uint32_t sm[];
    float* s = (float*)sm;
    uint32_t* su = sm;
    uint32_t* Qs = sm + Q_OFF;
    uint32_t* Ks = sm + K_OFF;
    uint32_t* Vs = sm + V_OFF;
    float* mk = (float*)(sm + MK_OFF);

    const int bh = blockIdx.y, b = bh >> 4;
    const int q0 = blockIdx.x * 64;
    const int tid = threadIdx.x;
    const int warp = tid >> 5, lane = tid & 31;
    const int g = lane >> 2, t = lane & 3;
    const int wm = (warp & 3) * 16, wn = (warp >> 2) * 32;

    const uint32_t* qg = g_qt + (size_t)bh * NN * HD;
    const uint32_t* kg = g_kt + (size_t)bh * NN * HD;
    const uint32_t* vg = g_vt + (size_t)bh * NN * HD;

    for (int i = tid; i < NN; i += 256) mk[i] = mask[b * NN + i];

    {   // Q tile 64x64 words
        int r = tid >> 2, c = (tid & 3) * 4;
#pragma unroll
        for (int p = 0; p < 4; p++)
            *(uint4*)(Qs + r * QLD + c + p * 16) =
                *(const uint4*)(qg + (size_t)(q0 + r) * HD + c + p * 16);
    }
    __syncthreads();

    // preload all Q A-fragments for this warp's 16 rows (reused over all kt)
    uint32_t af[8][4];
#pragma unroll
    for (int ks = 0; ks < 8; ks++) {
        af[ks][0] = Qs[(wm + g) * QLD + ks * 8 + t];
        af[ks][1] = Qs[(wm + g + 8) * QLD + ks * 8 + t];
        af[ks][2] = Qs[(wm + g) * QLD + ks * 8 + t + 4];
        af[ks][3] = Qs[(wm + g + 8) * QLD + ks * 8 + t + 4];
    }

    // ---- S = Q K^T + mask_key ----
#pragma unroll 1
    for (int kt = 0; kt < 8; kt++) {
        __syncthreads();
        {
            int r = tid >> 2, c = (tid & 3) * 4;
#pragma unroll
            for (int p = 0; p < 4; p++)
                *(uint4*)(Ks + r * QLD + c + p * 16) =
                    *(const uint4*)(kg + (size_t)(kt * 64 + r) * HD + c + p * 16);
        }
        __syncthreads();

        float accs[4][4];
#pragma unroll
        for (int jn = 0; jn < 4; jn++)
#pragma unroll
            for (int c = 0; c < 4; c++) accs[jn][c] = 0.f;

#pragma unroll
        for (int ks = 0; ks < 8; ks++) {
            uint32_t bf[4][2];
#pragma unroll
            for (int jn = 0; jn < 4; jn++) {
                int cb = wn + jn * 8;
                bf[jn][0] = Ks[(cb + g) * QLD + ks * 8 + t];
                bf[jn][1] = Ks[(cb + g) * QLD + ks * 8 + t + 4];
            }
#pragma unroll
            for (int jn = 0; jn < 4; jn++) mma8(accs[jn], af[ks], bf[jn]);
        }
#pragma unroll
        for (int jn = 0; jn < 4; jn++) {
            int col = kt * 64 + wn + jn * 8 + 2 * t;
            s[(wm + g) * SLD + col] = accs[jn][0] + mk[col];
            s[(wm + g) * SLD + col + 1] = accs[jn][1] + mk[col + 1];
            s[(wm + g + 8) * SLD + col] = accs[jn][2] + mk[col];
            s[(wm + g + 8) * SLD + col + 1] = accs[jn][3] + mk[col + 1];
        }
    }
    __syncthreads();

    // ---- softmax (fp32) + in-place conversion of P to tf32 bits ----
    for (int r = warp; r < 64; r += 8) {
        float* row = s + r * SLD;
        float m = -1e30f;
        for (int j = lane; j < NN; j += 32) m = fmaxf(m, row[j]);
#pragma unroll
        for (int o = 16; o > 0; o >>= 1)
            m = fmaxf(m, __shfl_xor_sync(0xffffffffu, m, o));
        float l = 0.f;
        for (int j = lane; j < NN; j += 32) {
            float e = __expf(row[j] - m);
            row[j] = e;
            l += e;
        }
#pragma unroll
        for (int o = 16; o > 0; o >>= 1) l += __shfl_xor_sync(0xffffffffu, l, o);
        float inv = 1.0f / l;
        uint32_t* urow = (uint32_t*)row;
        for (int j = lane; j < NN; j += 32) urow[j] = f2t(row[j] * inv);
    }

    // ---- O = P V ----
    float acco[4][4];
#pragma unroll
    for (int jn = 0; jn < 4; jn++)
#pragma unroll
        for (int c = 0; c < 4; c++) acco[jn][c] = 0.f;

#pragma unroll 1
    for (int vt = 0; vt < 8; vt++) {
        __syncthreads();
        {
            int r = tid >> 2, c = (tid & 3) * 4;
#pragma unroll
            for (int p = 0; p < 4; p++)
                *(uint4*)(Vs + r * VLD + c + p * 16) =
                    *(const uint4*)(vg + (size_t)(vt * 64 + r) * HD + c + p * 16);
        }
        __syncthreads();

#pragma unroll
        for (int ks = 0; ks < 8; ks++) {
            int kk = vt * 64 + ks * 8;
            uint32_t pa[4];
            pa[0] = su[(wm + g) * SLD + kk + t];
            pa[1] = su[(wm + g + 8) * SLD + kk + t];
            pa[2] = su[(wm + g) * SLD + kk + t + 4];
            pa[3] = su[(wm + g + 8) * SLD + kk + t + 4];
            uint32_t bf[4][2];
#pragma unroll
            for (int jn = 0; jn < 4; jn++) {
                int cb = wn + jn * 8;
                bf[jn][0] = Vs[(ks * 8 + t) * VLD + cb + g];
                bf[jn][1] = Vs[(ks * 8 + t + 4) * VLD + cb + g];
            }
#pragma unroll
            for (int jn = 0; jn < 4; jn++) mma8(acco[jn], pa, bf[jn]);
        }
    }

    // epilogue -> g_ot [B*N, C] as tf32 bits (input to proj GEMM)
    const int h = bh & (HH - 1);
    uint32_t* og = g_ot + (size_t)(b * NN + q0 + wm + g) * CC + h * HD;
#pragma unroll
    for (int jn = 0; jn < 4; jn++) {
        int col = wn + jn * 8 + 2 * t;
        *(uint2*)(og + col) = make_uint2(f2t(acco[jn][0]), f2t(acco[jn][1]));
        *(uint2*)(og + (size_t)8 * CC + col) =
            make_uint2(f2t(acco[jn][2]), f2t(acco[jn][3]));
    }
}

// ---------------------------------------------------------------------------
extern "C" void kernel_launch(void* const* d_in, const int* in_sizes, int n_in,
                              void* d_out, int out_size) {
    const float* x = (const float*)d_in[0];       // [B,N,C]
    const float* mask = (const float*)d_in[1];    // [B,N]
    const float* W_qkv = (const float*)d_in[2];   // [3C,C]
    const float* W_proj = (const float*)d_in[3];  // [C,C]
    const float* b_proj = (const float*)d_in[4];  // [C]
    float* out = (float*)d_out;                   // [B,N,C]

    static bool once = false;
    if (!once) {
        cudaFuncSetAttribute(attn_tf32, cudaFuncAttributeMaxDynamicSharedMemorySize,
                             ATTN_SMEM);
        once = true;
    }

    // 0) operand conversion to tf32 bits
    cvt_kernel<0><<<MTOT * CC / 1024, 256>>>(x);
    cvt_kernel<1><<<3 * CC * CC / 1024, 256>>>(W_qkv);
    cvt_kernel<2><<<CC * CC / 1024, 256>>>(W_proj);

    // 1) QKV projection (tensor cores) + scatter (q scaled, tf32 bits)
    gemm_tf32<0><<<dim3(3 * CC / 128, MTOT / 128), 128>>>(nullptr, nullptr);
    // 2) attention (tensor cores)
    attn_tf32<<<dim3(NN / 64, BB * HH), 256, ATTN_SMEM>>>(mask);
    // 3) output projection + bias
    gemm_tf32<1><<<dim3(CC / 128, MTOT / 128), 128>>>(b_proj, out);
}

// round 3
// speedup vs baseline: 4.2215x; 1.3622x over previous
#include <cuda_runtime.h>
#include <cstdint>

#define BB 32
#define NN 512
#define CC 1024
#define HH 16
#define HD 64
#define SCALE 0.125f
#define MTOT (BB * NN)   // 16384

// tf32-bit scratch (uint32 holds tf32-rounded fp32 bit pattern)
__device__ uint32_t g_xt[MTOT * CC];
__device__ uint32_t g_wqkvt[3 * CC * CC];
__device__ uint32_t g_wpt[CC * CC];
__device__ uint32_t g_qt[BB * HH * NN * HD];
__device__ uint32_t g_kt[BB * HH * NN * HD];
__device__ uint32_t g_vt[BB * HH * NN * HD];
__device__ uint32_t g_ot[MTOT * CC];

__device__ __forceinline__ uint32_t f2t(float x) {
    uint32_t y;
    asm("cvt.rna.tf32.f32 %0, %1;" : "=r"(y) : "f"(x));
    return y;
}

__device__ __forceinline__ void mma8(float* d, const uint32_t* a, const uint32_t* b) {
    asm volatile(
        "mma.sync.aligned.m16n8k8.row.col.f32.tf32.tf32.f32 "
        "{%0,%1,%2,%3}, {%4,%5,%6,%7}, {%8,%9}, {%0,%1,%2,%3};"
        : "+f"(d[0]), "+f"(d[1]), "+f"(d[2]), "+f"(d[3])
        : "r"(a[0]), "r"(a[1]), "r"(a[2]), "r"(a[3]), "r"(b[0]), "r"(b[1]));
}

__device__ __forceinline__ void cpa16(uint32_t* dst, const uint32_t* src) {
    uint32_t d = (uint32_t)__cvta_generic_to_shared(dst);
    asm volatile("cp.async.cg.shared.global [%0], [%1], 16;" :: "r"(d), "l"(src));
}

// ---------------------------------------------------------------------------
// fp32 -> tf32 bits elementwise
// ---------------------------------------------------------------------------
template <int DST>
__global__ void cvt_kernel(const float* __restrict__ src) {
    uint32_t* dst = (DST == 0) ? g_xt : (DST == 1) ? g_wqkvt : g_wpt;
    int i = (blockIdx.x * 256 + threadIdx.x) * 4;
    float4 v = *(const float4*)(src + i);
    *(uint4*)(dst + i) = make_uint4(f2t(v.x), f2t(v.y), f2t(v.z), f2t(v.w));
}

// ---------------------------------------------------------------------------
// tf32 tensor-core GEMM, 3-stage cp.async pipeline.
// C[M,Nout] = A[M,1024] * W[Nout,1024]^T ; BM=BN=128, BK=16, 128 thr, 4 warps
// MODE 0: A=g_xt, W=g_wqkvt -> scatter tf32 bits into g_qt/g_kt/g_vt
// MODE 1: A=g_ot, W=g_wpt   -> fp32 out + bias
// ---------------------------------------------------------------------------
#define SA 20   // smem row stride 16+4: (20*g + t) distinct mod 32

template <int MODE>
__global__ __launch_bounds__(128, 2)
void gemm_tf32(const float* __restrict__ bias, float* __restrict__ out) {
    const uint32_t* A = (MODE == 0) ? g_xt : g_ot;
    const uint32_t* W = (MODE == 0) ? g_wqkvt : g_wpt;
    const int tileN = blockIdx.x * 128;
    const int tileM = blockIdx.y * 128;

    __shared__ uint32_t As[3][128 * SA];
    __shared__ uint32_t Bs[3][128 * SA];

    const int tid = threadIdx.x, warp = tid >> 5, lane = tid & 31;
    const int g = lane >> 2, t = lane & 3;
    const int wm = (warp & 1) * 64, wn = (warp >> 1) * 64;
    const int lr = tid >> 2, lc = (tid & 3) << 2;

    const uint32_t* Ap = A + (size_t)(tileM + lr) * CC + lc;
    const uint32_t* Wp = W + (size_t)(tileN + lr) * CC + lc;

    auto issue = [&](int kt) {
        int st = kt % 3;
        int off = kt * 16;
#pragma unroll
        for (int i = 0; i < 4; i++) {
            cpa16(&As[st][(lr + i * 32) * SA + lc], Ap + (size_t)(i * 32) * CC + off);
            cpa16(&Bs[st][(lr + i * 32) * SA + lc], Wp + (size_t)(i * 32) * CC + off);
        }
        asm volatile("cp.async.commit_group;");
    };

    float acc[4][8][4];
#pragma unroll
    for (int im = 0; im < 4; im++)
#pragma unroll
        for (int jn = 0; jn < 8; jn++)
#pragma unroll
            for (int c = 0; c < 4; c++) acc[im][jn][c] = 0.f;

    issue(0);
    issue(1);

#pragma unroll 1
    for (int kt = 0; kt < 64; kt++) {
        if (kt < 62) {
            issue(kt + 2);
            asm volatile("cp.async.wait_group 2;");
        } else if (kt == 62) {
            asm volatile("cp.async.wait_group 1;");
        } else {
            asm volatile("cp.async.wait_group 0;");
        }
        __syncthreads();
        const uint32_t* Ac = As[kt % 3];
        const uint32_t* Bc = Bs[kt % 3];
#pragma unroll
        for (int ks = 0; ks < 2; ks++) {
            const int k0 = ks * 8;
            uint32_t af[4][4], bf[8][2];
#pragma unroll
            for (int im = 0; im < 4; im++) {
                int rb = wm + im * 16;
                af[im][0] = Ac[(rb + g) * SA + k0 + t];
                af[im][1] = Ac[(rb + g + 8) * SA + k0 + t];
                af[im][2] = Ac[(rb + g) * SA + k0 + t + 4];
                af[im][3] = Ac[(rb + g + 8) * SA + k0 + t + 4];
            }
#pragma unroll
            for (int jn = 0; jn < 8; jn++) {
                int cb = wn + jn * 8;
                bf[jn][0] = Bc[(cb + g) * SA + k0 + t];
                bf[jn][1] = Bc[(cb + g) * SA + k0 + t + 4];
            }
#pragma unroll
            for (int im = 0; im < 4; im++)
#pragma unroll
                for (int jn = 0; jn < 8; jn++) mma8(acc[im][jn], af[im], bf[jn]);
        }
        __syncthreads();
    }

    if (MODE == 0) {
        const int colbase = tileN + wn;           // multiple of 64
        const int which = colbase >> 10;          // 0=q 1=k 2=v
        const int h = (colbase >> 6) & (HH - 1);
        uint32_t* dst = (which == 0) ? g_qt : (which == 1) ? g_kt : g_vt;
        const float sc = (which == 0) ? SCALE : 1.0f;
#pragma unroll
        for (int im = 0; im < 4; im++) {
            int r0 = tileM + wm + im * 16 + g;
#pragma unroll
            for (int rr = 0; rr < 2; rr++) {
                int row = r0 + rr * 8;
                int b = row >> 9, n = row & (NN - 1);
                uint32_t* dp = dst + ((size_t)(b * HH + h) * NN + n) * HD;
#pragma unroll
                for (int jn = 0; jn < 8; jn++) {
                    int hd = jn * 8 + 2 * t;
                    uint2 v = make_uint2(f2t(acc[im][jn][rr * 2 + 0] * sc),
                                         f2t(acc[im][jn][rr * 2 + 1] * sc));
                    *(uint2*)(dp + hd) = v;
                }
            }
        }
    } else {
#pragma unroll
        for (int jn = 0; jn < 8; jn++) {
            int col = tileN + wn + jn * 8 + 2 * t;
            float2 bi = *(const float2*)(bias + col);
#pragma unroll
            for (int im = 0; im < 4; im++) {
                int r0 = tileM + wm + im * 16 + g;
                float2 v0 = make_float2(acc[im][jn][0] + bi.x, acc[im][jn][1] + bi.y);
                float2 v1 = make_float2(acc[im][jn][2] + bi.x, acc[im][jn][3] + bi.y);
                *(float2*)(out + (size_t)r0 * CC + col) = v0;
                *(float2*)(out + (size_t)(r0 + 8) * CC + col) = v1;
            }
        }
    }
}

// ---------------------------------------------------------------------------
// Flash attention: block per (b,h, 128-query tile); 8 warps, warp owns 16
// full rows -> softmax is intra-warp only. Online max/sum over 8 K-tiles of
// 64. P goes through smem as tf32 bits for the PV mma. Only the key-side
// mask term is added (query-side term is a per-row constant -> cancels).
// ---------------------------------------------------------------------------
#define QT 128
#define KT 64
#define QLD 68   // k-contig frag loads: (68*g + t) % 32 = (4g+t) conflict-free
#define KLD 68
#define VLD 72   // n-contig frag loads: (72*t + g) % 32 = (8t+g) conflict-free
#define PLD 68

#define AQ_OFF 0
#define AK_OFF (AQ_OFF + QT * QLD)
#define AV_OFF (AK_OFF + KT * KLD)
#define AP_OFF (AV_OFF + KT * VLD)
#define AMK_OFF (AP_OFF + QT * PLD)
#define ATTN_WORDS (AMK_OFF + 512)
#define ATTN_SMEM (ATTN_WORDS * 4)   // 107,520 B -> 2 CTAs/SM

__global__ __launch_bounds__(256, 2)
void attn_flash(const float* __restrict__ mask) {
    extern __shared__ uint32_t sm[];
    uint32_t* Qs = sm + AQ_OFF;
    uint32_t* Ks = sm + AK_OFF;
    uint32_t* Vs = sm + AV_OFF;
    uint32_t* Ps = sm + AP_OFF;
    float* mk = (float*)(sm + AMK_OFF);

    const int bh = blockIdx.y, b = bh >> 4, h = bh & (HH - 1);
    const int q0 = blockIdx.x * QT;
    const int tid = threadIdx.x, warp = tid >> 5, lane = tid & 31;
    const int g = lane >> 2, t = lane & 3;
    const int wr = warp * 16;

    const uint32_t* qg = g_qt + (size_t)bh * NN * HD;
    const uint32_t* kg = g_kt + (size_t)bh * NN * HD;
    const uint32_t* vg = g_vt + (size_t)bh * NN * HD;

    for (int i = tid; i < NN; i += 256) mk[i] = mask[b * NN + i];

    {   // Q tile: 128 rows x 64 words; 256 threads x 8 uint4
        int r = tid >> 1, c = (tid & 1) * 32;
        const uint32_t* src = qg + (size_t)(q0 + r) * HD + c;
        uint32_t* dst = Qs + r * QLD + c;
#pragma unroll
        for (int p = 0; p < 8; p++)
            *(uint4*)(dst + p * 4) = *(const uint4*)(src + p * 4);
    }

    float m_prev[2] = {-1e30f, -1e30f};
    float l_acc[2] = {0.f, 0.f};
    float o[8][4];
#pragma unroll
    for (int jn = 0; jn < 8; jn++)
#pragma unroll
        for (int c = 0; c < 4; c++) o[jn][c] = 0.f;

#pragma unroll 1
    for (int kt = 0; kt < 8; kt++) {
        __syncthreads();   // prev iter's mma reads of Ks/Vs/Ps done (iter 0: Q/mk ready)
        {   // load K,V tiles 64x64 words each
            int r = tid >> 2, c = (tid & 3) * 4;
            const uint32_t* ksrc = kg + (size_t)(kt * 64 + r) * HD;
            const uint32_t* vsrc = vg + (size_t)(kt * 64 + r) * HD;
#pragma unroll
            for (int p = 0; p < 4; p++) {
                *(uint4*)(Ks + r * KLD + c + p * 16) = *(const uint4*)(ksrc + c + p * 16);
                *(uint4*)(Vs + r * VLD + c + p * 16) = *(const uint4*)(vsrc + c + p * 16);
            }
        }
        __syncthreads();

        // ---- S = Q K^T (warp rows [wr,wr+16), cols 0..63) ----
        float accs[8][4];
#pragma unroll
        for (int jn = 0; jn < 8; jn++)
#pragma unroll
            for (int c = 0; c < 4; c++) accs[jn][c] = 0.f;

#pragma unroll
        for (int ks = 0; ks < 8; ks++) {
            int k0 = ks * 8;
            uint32_t af[4];
            af[0] = Qs[(wr + g) * QLD + k0 + t];
            af[1] = Qs[(wr + g + 8) * QLD + k0 + t];
            af[2] = Qs[(wr + g) * QLD + k0 + t + 4];
            af[3] = Qs[(wr + g + 8) * QLD + k0 + t + 4];
#pragma unroll
            for (int jn = 0; jn < 8; jn++) {
                uint32_t bf[2];
                bf[0] = Ks[(jn * 8 + g) * KLD + k0 + t];
                bf[1] = Ks[(jn * 8 + g) * KLD + k0 + t + 4];
                mma8(accs[jn], af, bf);
            }
        }

        // ---- online softmax update (rows g, g+8; reduce over t lanes) ----
        float tmax0 = -1e30f, tmax1 = -1e30f;
#pragma unroll
        for (int jn = 0; jn < 8; jn++) {
            int col = kt * 64 + jn * 8 + 2 * t;
            float mk0 = mk[col], mk1 = mk[col + 1];
            accs[jn][0] += mk0; accs[jn][1] += mk1;
            accs[jn][2] += mk0; accs[jn][3] += mk1;
            tmax0 = fmaxf(tmax0, fmaxf(accs[jn][0], accs[jn][1]));
            tmax1 = fmaxf(tmax1, fmaxf(accs[jn][2], accs[jn][3]));
        }
#pragma unroll
        for (int d = 1; d < 4; d <<= 1) {
            tmax0 = fmaxf(tmax0, __shfl_xor_sync(0xffffffffu, tmax0, d));
            tmax1 = fmaxf(tmax1, __shfl_xor_sync(0xffffffffu, tmax1, d));
        }
        float mn0 = fmaxf(m_prev[0], tmax0);
        float mn1 = fmaxf(m_prev[1], tmax1);
        float sc0 = __expf(m_prev[0] - mn0);
        float sc1 = __expf(m_prev[1] - mn1);
        m_prev[0] = mn0; m_prev[1] = mn1;

        float ts0 = 0.f, ts1 = 0.f;
#pragma unroll
        for (int jn = 0; jn < 8; jn++) {
            float p0 = __expf(accs[jn][0] - mn0);
            float p1 = __expf(accs[jn][1] - mn0);
            float p2 = __expf(accs[jn][2] - mn1);
            float p3 = __expf(accs[jn][3] - mn1);
            ts0 += p0 + p1; ts1 += p2 + p3;
            int col = jn * 8 + 2 * t;
            *(uint2*)&Ps[(wr + g) * PLD + col] = make_uint2(f2t(p0), f2t(p1));
            *(uint2*)&Ps[(wr + g + 8) * PLD + col] = make_uint2(f2t(p2), f2t(p3));
        }
#pragma unroll
        for (int d = 1; d < 4; d <<= 1) {
            ts0 += __shfl_xor_sync(0xffffffffu, ts0, d);
            ts1 += __shfl_xor_sync(0xffffffffu, ts1, d);
        }
        l_acc[0] = l_acc[0] * sc0 + ts0;
        l_acc[1] = l_acc[1] * sc1 + ts1;
#pragma unroll
        for (int jn = 0; jn < 8; jn++) {
            o[jn][0] *= sc0; o[jn][1] *= sc0;
            o[jn][2] *= sc1; o[jn][3] *= sc1;
        }
        __syncthreads();   // Ps ready for all warps

        // ---- O += P V ----
#pragma unroll
        for (int ks = 0; ks < 8; ks++) {
            int k0 = ks * 8;
            uint32_t pa[4];
            pa[0] = Ps[(wr + g) * PLD + k0 + t];
            pa[1] = Ps[(wr + g + 8) * PLD + k0 + t];
            pa[2] = Ps[(wr + g) * PLD + k0 + t + 4];
            pa[3] = Ps[(wr + g + 8) * PLD + k0 + t + 4];
#pragma unroll
            for (int jn = 0; jn < 8; jn++) {
                uint32_t bf[2];
                bf[0] = Vs[(k0 + t) * VLD + jn * 8 + g];
                bf[1] = Vs[(k0 + t + 4) * VLD + jn * 8 + g];
                mma8(o[jn], pa, bf);
            }
        }
    }

    // ---- epilogue: normalize, write tf32 bits to g_ot [B*N, C] ----
    float inv0 = 1.0f / l_acc[0], inv1 = 1.0f / l_acc[1];
    uint32_t* og = g_ot + (size_t)(b * NN + q0 + wr + g) * CC + h * HD;
#pragma unroll
    for (int jn = 0; jn < 8; jn++) {
        int col = jn * 8 + 2 * t;
        *(uint2*)(og + col) =
            make_uint2(f2t(o[jn][0] * inv0), f2t(o[jn][1] * inv0));
        *(uint2*)(og + (size_t)8 * CC + col) =
            make_uint2(f2t(o[jn][2] * inv1), f2t(o[jn][3] * inv1));
    }
}

// ---------------------------------------------------------------------------
extern "C" void kernel_launch(void* const* d_in, const int* in_sizes, int n_in,
                              void* d_out, int out_size) {
    const float* x = (const float*)d_in[0];       // [B,N,C]
    const float* mask = (const float*)d_in[1];    // [B,N]
    const float* W_qkv = (const float*)d_in[2];   // [3C,C]
    const float* W_proj = (const float*)d_in[3];  // [C,C]
    const float* b_proj = (const float*)d_in[4];  // [C]
    float* out = (float*)d_out;                   // [B,N,C]

    static bool once = false;
    if (!once) {
        cudaFuncSetAttribute(attn_flash, cudaFuncAttributeMaxDynamicSharedMemorySize,
                             ATTN_SMEM);
        once = true;
    }

    cvt_kernel<0><<<MTOT * CC / 1024, 256>>>(x);
    cvt_kernel<1><<<3 * CC * CC / 1024, 256>>>(W_qkv);
    cvt_kernel<2><<<CC * CC / 1024, 256>>>(W_proj);

    gemm_tf32<0><<<dim3(3 * CC / 128, MTOT / 128), 128>>>(nullptr, nullptr);
    attn_flash<<<dim3(NN / QT, BB * HH), 256, ATTN_SMEM>>>(mask);
    gemm_tf32<1><<<dim3(CC / 128, MTOT / 128), 128>>>(b_proj, out);
}

// round 4
// speedup vs baseline: 8.1042x; 1.9197x over previous
#include <cuda_runtime.h>
#include <cuda_fp16.h>
#include <cstdint>

#define BB 32
#define NN 512
#define CC 1024
#define HH 16
#define HD 64
#define SCALE 0.125f
#define MTOT (BB * NN)   // 16384
#define CH (CC / 2)      // 512 packed half2 words per row

// packed-half2 scratch (uint32 = 2 fp16)
__device__ uint32_t g_xh[MTOT * CH];
__device__ uint32_t g_wqkvh[3 * CC * CH];
__device__ uint32_t g_wph[CC * CH];
__device__ uint32_t g_qh[BB * HH * NN * HD / 2];
__device__ uint32_t g_kh[BB * HH * NN * HD / 2];
__device__ uint32_t g_vh[BB * HH * NN * HD / 2];
__device__ uint32_t g_oh[MTOT * CH];

__device__ __forceinline__ uint32_t packh2(float a, float b) {
    __half2 h = __floats2half2_rn(a, b);
    return *(uint32_t*)&h;
}

// m16n8k16 fp16 mma, fp32 accumulate
__device__ __forceinline__ void mma16(float* d, const uint32_t* a, const uint32_t* b) {
    asm volatile(
        "mma.sync.aligned.m16n8k16.row.col.f32.f16.f16.f32 "
        "{%0,%1,%2,%3}, {%4,%5,%6,%7}, {%8,%9}, {%0,%1,%2,%3};"
        : "+f"(d[0]), "+f"(d[1]), "+f"(d[2]), "+f"(d[3])
        : "r"(a[0]), "r"(a[1]), "r"(a[2]), "r"(a[3]), "r"(b[0]), "r"(b[1]));
}

__device__ __forceinline__ void ldmx2t(uint32_t& r0, uint32_t& r1, uint32_t addr) {
    asm volatile("ldmatrix.sync.aligned.m8n8.x2.trans.shared.b16 {%0,%1}, [%2];"
                 : "=r"(r0), "=r"(r1) : "r"(addr));
}

__device__ __forceinline__ void cpa16(uint32_t* dst, const uint32_t* src) {
    uint32_t d = (uint32_t)__cvta_generic_to_shared(dst);
    asm volatile("cp.async.cg.shared.global [%0], [%1], 16;" :: "r"(d), "l"(src));
}

// ---------------------------------------------------------------------------
// fp32 -> packed half2
// ---------------------------------------------------------------------------
template <int DST>
__global__ void cvt_kernel(const float* __restrict__ src) {
    uint32_t* dst = (DST == 0) ? g_xh : (DST == 1) ? g_wqkvh : g_wph;
    int i = (blockIdx.x * 256 + threadIdx.x) * 4;   // float index
    float4 v = *(const float4*)(src + i);
    *(uint2*)(dst + i / 2) = make_uint2(packh2(v.x, v.y), packh2(v.z, v.w));
}

// ---------------------------------------------------------------------------
// fp16 tensor-core GEMM, 3-stage cp.async pipeline.
// C[M,Nout] = A[M,1024] * W[Nout,1024]^T ; BM=BN=128, BK=16 words (32 halves)
// 128 threads (4 warps), warp tile 64x64.
// MODE 0: A=g_xh, W=g_wqkvh -> scatter packed halves into g_qh/g_kh/g_vh
// MODE 1: A=g_oh, W=g_wph   -> fp32 out + bias
// ---------------------------------------------------------------------------
#define SA 20   // smem row stride 16+4 words: (20*g+t) distinct mod 32

template <int MODE>
__global__ __launch_bounds__(128, 2)
void gemm_h(const float* __restrict__ bias, float* __restrict__ out) {
    const uint32_t* A = (MODE == 0) ? g_xh : g_oh;
    const uint32_t* W = (MODE == 0) ? g_wqkvh : g_wph;
    const int tileN = blockIdx.x * 128;
    const int tileM = blockIdx.y * 128;

    __shared__ uint32_t As[3][128 * SA];
    __shared__ uint32_t Bs[3][128 * SA];

    const int tid = threadIdx.x, warp = tid >> 5, lane = tid & 31;
    const int g = lane >> 2, t = lane & 3;
    const int wm = (warp & 1) * 64, wn = (warp >> 1) * 64;
    const int lr = tid >> 2, lc = (tid & 3) << 2;

    const uint32_t* Ap = A + (size_t)(tileM + lr) * CH + lc;
    const uint32_t* Wp = W + (size_t)(tileN + lr) * CH + lc;

    auto issue = [&](int kt) {
        int st = kt % 3;
        int off = kt * 16;
#pragma unroll
        for (int i = 0; i < 4; i++) {
            cpa16(&As[st][(lr + i * 32) * SA + lc], Ap + (size_t)(i * 32) * CH + off);
            cpa16(&Bs[st][(lr + i * 32) * SA + lc], Wp + (size_t)(i * 32) * CH + off);
        }
        asm volatile("cp.async.commit_group;");
    };

    float acc[4][8][4];
#pragma unroll
    for (int im = 0; im < 4; im++)
#pragma unroll
        for (int jn = 0; jn < 8; jn++)
#pragma unroll
            for (int c = 0; c < 4; c++) acc[im][jn][c] = 0.f;

    issue(0);
    issue(1);

#pragma unroll 1
    for (int kt = 0; kt < 32; kt++) {
        if (kt < 30) {
            issue(kt + 2);
            asm volatile("cp.async.wait_group 2;");
        } else if (kt == 30) {
            asm volatile("cp.async.wait_group 1;");
        } else {
            asm volatile("cp.async.wait_group 0;");
        }
        __syncthreads();
        const uint32_t* Ac = As[kt % 3];
        const uint32_t* Bc = Bs[kt % 3];
#pragma unroll
        for (int ks = 0; ks < 2; ks++) {   // 2 x k16 (8 words each)
            const int k0 = ks * 8;
            uint32_t af[4][4], bf[8][2];
#pragma unroll
            for (int im = 0; im < 4; im++) {
                int rb = wm + im * 16;
                af[im][0] = Ac[(rb + g) * SA + k0 + t];
                af[im][1] = Ac[(rb + g + 8) * SA + k0 + t];
                af[im][2] = Ac[(rb + g) * SA + k0 + t + 4];
                af[im][3] = Ac[(rb + g + 8) * SA + k0 + t + 4];
            }
#pragma unroll
            for (int jn = 0; jn < 8; jn++) {
                int cb = wn + jn * 8;
                bf[jn][0] = Bc[(cb + g) * SA + k0 + t];
                bf[jn][1] = Bc[(cb + g) * SA + k0 + t + 4];
            }
#pragma unroll
            for (int im = 0; im < 4; im++)
#pragma unroll
                for (int jn = 0; jn < 8; jn++) mma16(acc[im][jn], af[im], bf[jn]);
        }
        __syncthreads();
    }

    if (MODE == 0) {
        const int colbase = tileN + wn;           // multiple of 64
        const int which = colbase >> 10;          // 0=q 1=k 2=v
        const int h = (colbase >> 6) & (HH - 1);
        uint32_t* dst = (which == 0) ? g_qh : (which == 1) ? g_kh : g_vh;
        const float sc = (which == 0) ? SCALE : 1.0f;
#pragma unroll
        for (int im = 0; im < 4; im++) {
            int r0 = tileM + wm + im * 16 + g;
#pragma unroll
            for (int rr = 0; rr < 2; rr++) {
                int row = r0 + rr * 8;
                int b = row >> 9, n = row & (NN - 1);
                uint32_t* dp = dst + ((size_t)(b * HH + h) * NN + n) * (HD / 2);
#pragma unroll
                for (int jn = 0; jn < 8; jn++)
                    dp[jn * 4 + t] = packh2(acc[im][jn][rr * 2 + 0] * sc,
                                            acc[im][jn][rr * 2 + 1] * sc);
            }
        }
    } else {
#pragma unroll
        for (int jn = 0; jn < 8; jn++) {
            int col = tileN + wn + jn * 8 + 2 * t;
            float2 bi = *(const float2*)(bias + col);
#pragma unroll
            for (int im = 0; im < 4; im++) {
                int r0 = tileM + wm + im * 16 + g;
                float2 v0 = make_float2(acc[im][jn][0] + bi.x, acc[im][jn][1] + bi.y);
                float2 v1 = make_float2(acc[im][jn][2] + bi.x, acc[im][jn][3] + bi.y);
                *(float2*)(out + (size_t)r0 * CC + col) = v0;
                *(float2*)(out + (size_t)(r0 + 8) * CC + col) = v1;
            }
        }
    }
}

// ---------------------------------------------------------------------------
// Flash attention (fp16 operands, fp32 softmax/accum).
// Block per (b,h, 128-query tile); 8 warps; warp owns 16 full rows.
// V fragments via ldmatrix.x2.trans from row-major [key][hd] tile.
// ---------------------------------------------------------------------------
#define QT 128
#define QLD 36   // 32 + 4 words
#define KLD 36
#define VLD 36
#define PLD 36

#define AQ_OFF 0
#define AK_OFF (AQ_OFF + QT * QLD)
#define AV_OFF (AK_OFF + 64 * KLD)
#define AP_OFF (AV_OFF + 64 * VLD)
#define AMK_OFF (AP_OFF + QT * PLD)
#define ATTN_WORDS (AMK_OFF + 512)
#define ATTN_SMEM (ATTN_WORDS * 4)   // 57,344 B

__global__ __launch_bounds__(256, 2)
void attn_flash(const float* __restrict__ mask) {
    extern __shared__ uint32_t sm[];
    uint32_t* Qs = sm + AQ_OFF;
    uint32_t* Ks = sm + AK_OFF;
    uint32_t* Vs = sm + AV_OFF;
    uint32_t* Ps = sm + AP_OFF;
    float* mk = (float*)(sm + AMK_OFF);

    const int bh = blockIdx.y, b = bh >> 4, h = bh & (HH - 1);
    const int q0 = blockIdx.x * QT;
    const int tid = threadIdx.x, warp = tid >> 5, lane = tid & 31;
    const int g = lane >> 2, t = lane & 3;
    const int wr = warp * 16;

    const uint32_t* qg = g_qh + (size_t)bh * NN * (HD / 2);
    const uint32_t* kg = g_kh + (size_t)bh * NN * (HD / 2);
    const uint32_t* vg = g_vh + (size_t)bh * NN * (HD / 2);
    const uint32_t vs_base = (uint32_t)__cvta_generic_to_shared(Vs);

    for (int i = tid; i < NN; i += 256) mk[i] = mask[b * NN + i];

    {   // Q tile: 128 rows x 32 words
        int r = tid >> 1, c = (tid & 1) * 16;
        const uint32_t* src = qg + (size_t)(q0 + r) * (HD / 2) + c;
        uint32_t* dst = Qs + r * QLD + c;
#pragma unroll
        for (int p = 0; p < 4; p++)
            *(uint4*)(dst + p * 4) = *(const uint4*)(src + p * 4);
    }

    float m_prev[2] = {-1e30f, -1e30f};
    float l_acc[2] = {0.f, 0.f};
    float o[8][4];
#pragma unroll
    for (int jn = 0; jn < 8; jn++)
#pragma unroll
        for (int c = 0; c < 4; c++) o[jn][c] = 0.f;

#pragma unroll 1
    for (int kt = 0; kt < 8; kt++) {
        __syncthreads();
        {   // K,V tiles: 64 rows x 32 words each
            int r = tid >> 2, c = (tid & 3) * 8;
            const uint32_t* ksrc = kg + (size_t)(kt * 64 + r) * (HD / 2) + c;
            const uint32_t* vsrc = vg + (size_t)(kt * 64 + r) * (HD / 2) + c;
            *(uint4*)(Ks + r * KLD + c) = *(const uint4*)(ksrc);
            *(uint4*)(Ks + r * KLD + c + 4) = *(const uint4*)(ksrc + 4);
            *(uint4*)(Vs + r * VLD + c) = *(const uint4*)(vsrc);
            *(uint4*)(Vs + r * VLD + c + 4) = *(const uint4*)(vsrc + 4);
        }
        __syncthreads();

        // ---- S = Q K^T (warp rows [wr,wr+16), 64 key cols) ----
        float accs[8][4];
#pragma unroll
        for (int jn = 0; jn < 8; jn++)
#pragma unroll
            for (int c = 0; c < 4; c++) accs[jn][c] = 0.f;

#pragma unroll
        for (int ks = 0; ks < 4; ks++) {   // 4 x k16 over HD=64
            int k0 = ks * 8;
            uint32_t af[4];
            af[0] = Qs[(wr + g) * QLD + k0 + t];
            af[1] = Qs[(wr + g + 8) * QLD + k0 + t];
            af[2] = Qs[(wr + g) * QLD + k0 + t + 4];
            af[3] = Qs[(wr + g + 8) * QLD + k0 + t + 4];
#pragma unroll
            for (int jn = 0; jn < 8; jn++) {
                uint32_t bf[2];
                bf[0] = Ks[(jn * 8 + g) * KLD + k0 + t];
                bf[1] = Ks[(jn * 8 + g) * KLD + k0 + t + 4];
                mma16(accs[jn], af, bf);
            }
        }

        // ---- online softmax (rows g, g+8; reduce over t lanes) ----
        float tmax0 = -1e30f, tmax1 = -1e30f;
#pragma unroll
        for (int jn = 0; jn < 8; jn++) {
            int col = kt * 64 + jn * 8 + 2 * t;
            float mk0 = mk[col], mk1 = mk[col + 1];
            accs[jn][0] += mk0; accs[jn][1] += mk1;
            accs[jn][2] += mk0; accs[jn][3] += mk1;
            tmax0 = fmaxf(tmax0, fmaxf(accs[jn][0], accs[jn][1]));
            tmax1 = fmaxf(tmax1, fmaxf(accs[jn][2], accs[jn][3]));
        }
#pragma unroll
        for (int d = 1; d < 4; d <<= 1) {
            tmax0 = fmaxf(tmax0, __shfl_xor_sync(0xffffffffu, tmax0, d));
            tmax1 = fmaxf(tmax1, __shfl_xor_sync(0xffffffffu, tmax1, d));
        }
        float mn0 = fmaxf(m_prev[0], tmax0);
        float mn1 = fmaxf(m_prev[1], tmax1);
        float sc0 = __expf(m_prev[0] - mn0);
        float sc1 = __expf(m_prev[1] - mn1);
        m_prev[0] = mn0; m_prev[1] = mn1;

        float ts0 = 0.f, ts1 = 0.f;
#pragma unroll
        for (int jn = 0; jn < 8; jn++) {
            float p0 = __expf(accs[jn][0] - mn0);
            float p1 = __expf(accs[jn][1] - mn0);
            float p2 = __expf(accs[jn][2] - mn1);
            float p3 = __expf(accs[jn][3] - mn1);
            ts0 += p0 + p1; ts1 += p2 + p3;
            Ps[(wr + g) * PLD + jn * 4 + t] = packh2(p0, p1);
            Ps[(wr + g + 8) * PLD + jn * 4 + t] = packh2(p2, p3);
        }
#pragma unroll
        for (int d = 1; d < 4; d <<= 1) {
            ts0 += __shfl_xor_sync(0xffffffffu, ts0, d);
            ts1 += __shfl_xor_sync(0xffffffffu, ts1, d);
        }
        l_acc[0] = l_acc[0] * sc0 + ts0;
        l_acc[1] = l_acc[1] * sc1 + ts1;
#pragma unroll
        for (int jn = 0; jn < 8; jn++) {
            o[jn][0] *= sc0; o[jn][1] *= sc0;
            o[jn][2] *= sc1; o[jn][3] *= sc1;
        }
        __syncthreads();   // Ps visible to all warps

        // ---- O += P V  (V frags via ldmatrix.trans) ----
#pragma unroll
        for (int ks = 0; ks < 4; ks++) {   // 4 x k16 over 64 keys
            int k0 = ks * 8;
            uint32_t pa[4];
            pa[0] = Ps[(wr + g) * PLD + k0 + t];
            pa[1] = Ps[(wr + g + 8) * PLD + k0 + t];
            pa[2] = Ps[(wr + g) * PLD + k0 + t + 4];
            pa[3] = Ps[(wr + g + 8) * PLD + k0 + t + 4];
            uint32_t vrow = vs_base + (uint32_t)(ks * 16 + (lane & 15)) * (VLD * 4);
#pragma unroll
            for (int jn = 0; jn < 8; jn++) {
                uint32_t bf0, bf1;
                ldmx2t(bf0, bf1, vrow + jn * 16);
                uint32_t bf[2] = {bf0, bf1};
                mma16(o[jn], pa, bf);
            }
        }
    }

    // ---- epilogue: normalize, pack half2 -> g_oh [B*N, CH] ----
    float inv0 = 1.0f / l_acc[0], inv1 = 1.0f / l_acc[1];
    uint32_t* og = g_oh + (size_t)(b * NN + q0 + wr + g) * CH + h * (HD / 2);
#pragma unroll
    for (int jn = 0; jn < 8; jn++) {
        og[jn * 4 + t] = packh2(o[jn][0] * inv0, o[jn][1] * inv0);
        og[(size_t)8 * CH + jn * 4 + t] = packh2(o[jn][2] * inv1, o[jn][3] * inv1);
    }
}

// ---------------------------------------------------------------------------
extern "C" void kernel_launch(void* const* d_in, const int* in_sizes, int n_in,
                              void* d_out, int out_size) {
    const float* x = (const float*)d_in[0];       // [B,N,C]
    const float* mask = (const float*)d_in[1];    // [B,N]
    const float* W_qkv = (const float*)d_in[2];   // [3C,C]
    const float* W_proj = (const float*)d_in[3];  // [C,C]
    const float* b_proj = (const float*)d_in[4];  // [C]
    float* out = (float*)d_out;                   // [B,N,C]

    static bool once = false;
    if (!once) {
        cudaFuncSetAttribute(attn_flash, cudaFuncAttributeMaxDynamicSharedMemorySize,
                             ATTN_SMEM);
        once = true;
    }

    cvt_kernel<0><<<MTOT * CC / 1024, 256>>>(x);
    cvt_kernel<1><<<3 * CC * CC / 1024, 256>>>(W_qkv);
    cvt_kernel<2><<<CC * CC / 1024, 256>>>(W_proj);

    gemm_h<0><<<dim3(3 * CC / 128, MTOT / 128), 128>>>(nullptr, nullptr);
    attn_flash<<<dim3(NN / QT, BB * HH), 256, ATTN_SMEM>>>(mask);
    gemm_h<1><<<dim3(CC / 128, MTOT / 128), 128>>>(b_proj, out);
}

// round 8
// speedup vs baseline: 8.8918x; 1.0972x over previous
#include <cuda_runtime.h>
#include <cuda_fp16.h>
#include <cstdint>

#define BB 32
#define NN 512
#define CC 1024
#define HH 16
#define HD 64
#define SCALE 0.125f
#define MTOT (BB * NN)   // 16384
#define CH (CC / 2)      // 512 packed half2 words per row

// packed-half2 scratch (uint32 = 2 fp16)
__device__ uint32_t g_xh[MTOT * CH];
__device__ uint32_t g_wqkvh[3 * CC * CH];
__device__ uint32_t g_wph[CC * CH];
__device__ uint32_t g_qh[BB * HH * NN * HD / 2];
__device__ uint32_t g_kh[BB * HH * NN * HD / 2];
__device__ uint32_t g_vh[BB * HH * NN * HD / 2];
__device__ uint32_t g_oh[MTOT * CH];

__device__ __forceinline__ uint32_t packh2(float a, float b) {
    __half2 h = __floats2half2_rn(a, b);
    return *(uint32_t*)&h;
}

// m16n8k16 fp16 mma, fp32 accumulate
__device__ __forceinline__ void mma16(float* d, const uint32_t* a, const uint32_t* b) {
    asm volatile(
        "mma.sync.aligned.m16n8k16.row.col.f32.f16.f16.f32 "
        "{%0,%1,%2,%3}, {%4,%5,%6,%7}, {%8,%9}, {%0,%1,%2,%3};"
        : "+f"(d[0]), "+f"(d[1]), "+f"(d[2]), "+f"(d[3])
        : "r"(a[0]), "r"(a[1]), "r"(a[2]), "r"(a[3]), "r"(b[0]), "r"(b[1]));
}

__device__ __forceinline__ void ldmx4(uint32_t* r, uint32_t addr) {
    asm volatile("ldmatrix.sync.aligned.m8n8.x4.shared.b16 {%0,%1,%2,%3}, [%4];"
                 : "=r"(r[0]), "=r"(r[1]), "=r"(r[2]), "=r"(r[3]) : "r"(addr));
}

__device__ __forceinline__ void ldmx4t(uint32_t* r, uint32_t addr) {
    asm volatile("ldmatrix.sync.aligned.m8n8.x4.trans.shared.b16 {%0,%1,%2,%3}, [%4];"
                 : "=r"(r[0]), "=r"(r[1]), "=r"(r[2]), "=r"(r[3]) : "r"(addr));
}

__device__ __forceinline__ void cpa16(uint32_t* dst, const uint32_t* src) {
    uint32_t d = (uint32_t)__cvta_generic_to_shared(dst);
    asm volatile("cp.async.cg.shared.global [%0], [%1], 16;" :: "r"(d), "l"(src));
}

__device__ __forceinline__ uint32_t s2u(const void* p) {
    uint32_t a;
    asm("{ .reg .u64 t; cvta.to.shared.u64 t, %1; cvt.u32.u64 %0, t; }"
        : "=r"(a) : "l"(p));
    return a;
}

// ---------------------------------------------------------------------------
// fp32 -> packed half2
// ---------------------------------------------------------------------------
template <int DST>
__global__ void cvt_kernel(const float* __restrict__ src) {
    uint32_t* dst = (DST == 0) ? g_xh : (DST == 1) ? g_wqkvh : g_wph;
    int i = (blockIdx.x * 256 + threadIdx.x) * 4;   // float index
    float4 v = *(const float4*)(src + i);
    *(uint2*)(dst + i / 2) = make_uint2(packh2(v.x, v.y), packh2(v.z, v.w));
}

// ---------------------------------------------------------------------------
// fp16 tensor-core GEMM, 3-stage cp.async pipeline, ldmatrix.x4 fragments.
// C[M,Nout] = A[M,1024] * W[Nout,1024]^T ; BM=BN=128, BK=16 words (32 halves)
// 128 threads (4 warps), warp tile 64x64.
// MODE 0: A=g_xh, W=g_wqkvh -> scatter packed halves into g_qh/g_kh/g_vh
// MODE 1: A=g_oh, W=g_wph   -> fp32 out + bias
// ---------------------------------------------------------------------------
#define SA 20   // smem row stride 16+4 words: ldmatrix phases hit banks 4r+c

template <int MODE>
__global__ __launch_bounds__(128, 2)
void gemm_h(const float* __restrict__ bias, float* __restrict__ out) {
    const uint32_t* A = (MODE == 0) ? g_xh : g_oh;
    const uint32_t* W = (MODE == 0) ? g_wqkvh : g_wph;
    const int tileN = blockIdx.x * 128;
    const int tileM = blockIdx.y * 128;

    __shared__ uint32_t As[3][128 * SA];
    __shared__ uint32_t Bs[3][128 * SA];

    const int tid = threadIdx.x, warp = tid >> 5, lane = tid & 31;
    const int g = lane >> 2, t = lane & 3;
    const int li = lane >> 3, l8 = lane & 7;      // ldmatrix: matrix idx, row
    const int wm = (warp & 1) * 64, wn = (warp >> 1) * 64;
    const int lr = tid >> 2, lc = (tid & 3) << 2;

    const uint32_t* Ap = A + (size_t)(tileM + lr) * CH + lc;
    const uint32_t* Wp = W + (size_t)(tileN + lr) * CH + lc;

    // per-lane ldmatrix byte offsets (within a stage buffer)
    // A: matrix i -> rows rb+(i&1)*8, k words +(i>>1)*4
    const uint32_t aoff = ((wm + (li & 1) * 8 + l8) * SA + (li >> 1) * 4) * 4;
    // B: matrix i -> rows cb+(i>>1)*8, k words +(i&1)*4  (covers 2 jn per x4)
    const uint32_t boff = ((wn + (li >> 1) * 8 + l8) * SA + (li & 1) * 4) * 4;

    auto issue = [&](int kt) {
        int st = kt % 3;
        int off = kt * 16;
#pragma unroll
        for (int i = 0; i < 4; i++) {
            cpa16(&As[st][(lr + i * 32) * SA + lc], Ap + (size_t)(i * 32) * CH + off);
            cpa16(&Bs[st][(lr + i * 32) * SA + lc], Wp + (size_t)(i * 32) * CH + off);
        }
        asm volatile("cp.async.commit_group;");
    };

    float acc[4][8][4];
#pragma unroll
    for (int im = 0; im < 4; im++)
#pragma unroll
        for (int jn = 0; jn < 8; jn++)
#pragma unroll
            for (int c = 0; c < 4; c++) acc[im][jn][c] = 0.f;

    issue(0);
    issue(1);

#pragma unroll 1
    for (int kt = 0; kt < 32; kt++) {
        if (kt < 30) {
            issue(kt + 2);
            asm volatile("cp.async.wait_group 2;");
        } else if (kt == 30) {
            asm volatile("cp.async.wait_group 1;");
        } else {
            asm volatile("cp.async.wait_group 0;");
        }
        __syncthreads();
        const uint32_t Acb = s2u(As[kt % 3]);
        const uint32_t Bcb = s2u(Bs[kt % 3]);
#pragma unroll
        for (int ks = 0; ks < 2; ks++) {   // 2 x k16 (8 words each)
            const uint32_t kb = ks * 8 * 4;
            uint32_t af[4][4], bf[8][2];
#pragma unroll
            for (int im = 0; im < 4; im++)
                ldmx4(af[im], Acb + aoff + (uint32_t)(im * 16 * SA) * 4 + kb);
#pragma unroll
            for (int p = 0; p < 4; p++) {
                uint32_t q[4];
                ldmx4(q, Bcb + boff + (uint32_t)(p * 16 * SA) * 4 + kb);
                bf[2 * p][0] = q[0]; bf[2 * p][1] = q[1];
                bf[2 * p + 1][0] = q[2]; bf[2 * p + 1][1] = q[3];
            }
#pragma unroll
            for (int im = 0; im < 4; im++)
#pragma unroll
                for (int jn = 0; jn < 8; jn++) mma16(acc[im][jn], af[im], bf[jn]);
        }
        __syncthreads();
    }

    if (MODE == 0) {
        const int colbase = tileN + wn;           // multiple of 64
        const int which = colbase >> 10;          // 0=q 1=k 2=v
        const int h = (colbase >> 6) & (HH - 1);
        uint32_t* dst = (which == 0) ? g_qh : (which == 1) ? g_kh : g_vh;
        const float sc = (which == 0) ? SCALE : 1.0f;
#pragma unroll
        for (int im = 0; im < 4; im++) {
            int r0 = tileM + wm + im * 16 + g;
#pragma unroll
            for (int rr = 0; rr < 2; rr++) {
                int row = r0 + rr * 8;
                int b = row >> 9, n = row & (NN - 1);
                uint32_t* dp = dst + ((size_t)(b * HH + h) * NN + n) * (HD / 2);
#pragma unroll
                for (int jn = 0; jn < 8; jn++)
                    dp[jn * 4 + t] = packh2(acc[im][jn][rr * 2 + 0] * sc,
                                            acc[im][jn][rr * 2 + 1] * sc);
            }
        }
    } else {
#pragma unroll
        for (int jn = 0; jn < 8; jn++) {
            int col = tileN + wn + jn * 8 + 2 * t;
            float2 bi = *(const float2*)(bias + col);
#pragma unroll
            for (int im = 0; im < 4; im++) {
                int r0 = tileM + wm + im * 16 + g;
                float2 v0 = make_float2(acc[im][jn][0] + bi.x, acc[im][jn][1] + bi.y);
                float2 v1 = make_float2(acc[im][jn][2] + bi.x, acc[im][jn][3] + bi.y);
                *(float2*)(out + (size_t)r0 * CC + col) = v0;
                *(float2*)(out + (size_t)(r0 + 8) * CC + col) = v1;
            }
        }
    }
}

// ---------------------------------------------------------------------------
// Flash attention (fp16 operands, fp32 softmax/accum), ldmatrix everywhere.
// Block per (b,h, 128-query tile); 8 warps; warp owns 16 full rows.
// ---------------------------------------------------------------------------
#define QT 128
#define QLD 36   // pads: ldmatrix phases -> banks (4r+c) / trans (36r+c), clean
#define KLD 36
#define VLD 36
#define PLD 36

#define AQ_OFF 0
#define AK_OFF (AQ_OFF + QT * QLD)
#define AV_OFF (AK_OFF + 64 * KLD)
#define AP_OFF (AV_OFF + 64 * VLD)
#define AMK_OFF (AP_OFF + QT * PLD)
#define ATTN_WORDS (AMK_OFF + 512)
#define ATTN_SMEM (ATTN_WORDS * 4)   // 57,344 B

__global__ __launch_bounds__(256, 2)
void attn_flash(const float* __restrict__ mask) {
    extern __shared__ uint32_t sm[];
    uint32_t* Qs = sm + AQ_OFF;
    uint32_t* Ks = sm + AK_OFF;
    uint32_t* Vs = sm + AV_OFF;
    uint32_t* Ps = sm + AP_OFF;
    float* mk = (float*)(sm + AMK_OFF);

    const int bh = blockIdx.y, b = bh >> 4, h = bh & (HH - 1);
    const int q0 = blockIdx.x * QT;
    const int tid = threadIdx.x, warp = tid >> 5, lane = tid & 31;
    const int g = lane >> 2, t = lane & 3;
    const int li = lane >> 3, l8 = lane & 7;
    const int wr = warp * 16;

    const uint32_t* qg = g_qh + (size_t)bh * NN * (HD / 2);
    const uint32_t* kg = g_kh + (size_t)bh * NN * (HD / 2);
    const uint32_t* vg = g_vh + (size_t)bh * NN * (HD / 2);

    const uint32_t Qsb = s2u(Qs), Ksb = s2u(Ks), Vsb = s2u(Vs), Psb = s2u(Ps);
    // A-style frag offsets (16 rows starting at wr)
    const uint32_t qoff = ((wr + (li & 1) * 8 + l8) * QLD + (li >> 1) * 4) * 4;
    const uint32_t poff = ((wr + (li & 1) * 8 + l8) * PLD + (li >> 1) * 4) * 4;
    // B-style frag offsets (keys; covers 2 jn per x4)
    const uint32_t koff = (((li >> 1) * 8 + l8) * KLD + (li & 1) * 4) * 4;
    // V trans frags: rows = keys, cols = hd; matrix i: rows +(i&1)*8, col +(i>>1)*16B
    const uint32_t voff = (((li & 1) * 8 + l8) * VLD) * 4 + (li >> 1) * 16;

    for (int i = tid; i < NN; i += 256) mk[i] = mask[b * NN + i];

    {   // Q tile: 128 rows x 32 words
        int r = tid >> 1, c = (tid & 1) * 16;
        const uint32_t* src = qg + (size_t)(q0 + r) * (HD / 2) + c;
        uint32_t* dst = Qs + r * QLD + c;
#pragma unroll
        for (int p = 0; p < 4; p++)
            *(uint4*)(dst + p * 4) = *(const uint4*)(src + p * 4);
    }

    float m_prev[2] = {-1e30f, -1e30f};
    float l_acc[2] = {0.f, 0.f};
    float o[8][4];
#pragma unroll
    for (int jn = 0; jn < 8; jn++)
#pragma unroll
        for (int c = 0; c < 4; c++) o[jn][c] = 0.f;

#pragma unroll 1
    for (int kt = 0; kt < 8; kt++) {
        __syncthreads();
        {   // K,V tiles: 64 rows x 32 words each
            int r = tid >> 2, c = (tid & 3) * 8;
            const uint32_t* ksrc = kg + (size_t)(kt * 64 + r) * (HD / 2) + c;
            const uint32_t* vsrc = vg + (size_t)(kt * 64 + r) * (HD / 2) + c;
            *(uint4*)(Ks + r * KLD + c) = *(const uint4*)(ksrc);
            *(uint4*)(Ks + r * KLD + c + 4) = *(const uint4*)(ksrc + 4);
            *(uint4*)(Vs + r * VLD + c) = *(const uint4*)(vsrc);
            *(uint4*)(Vs + r * VLD + c + 4) = *(const uint4*)(vsrc + 4);
        }
        __syncthreads();

        // ---- S = Q K^T (warp rows [wr,wr+16), 64 key cols) ----
        float accs[8][4];
#pragma unroll
        for (int jn = 0; jn < 8; jn++)
#pragma unroll
            for (int c = 0; c < 4; c++) accs[jn][c] = 0.f;

#pragma unroll
        for (int ks = 0; ks < 4; ks++) {   // 4 x k16 over HD=64
            const uint32_t kb = ks * 8 * 4;
            uint32_t af[4], bf[8][2];
            ldmx4(af, Qsb + qoff + kb);
#pragma unroll
            for (int p = 0; p < 4; p++) {
                uint32_t q[4];
                ldmx4(q, Ksb + koff + (uint32_t)(p * 16 * KLD) * 4 + kb);
                bf[2 * p][0] = q[0]; bf[2 * p][1] = q[1];
                bf[2 * p + 1][0] = q[2]; bf[2 * p + 1][1] = q[3];
            }
#pragma unroll
            for (int jn = 0; jn < 8; jn++) mma16(accs[jn], af, bf[jn]);
        }

        // ---- online softmax (rows g, g+8; reduce over t lanes) ----
        float tmax0 = -1e30f, tmax1 = -1e30f;
#pragma unroll
        for (int jn = 0; jn < 8; jn++) {
            int col = kt * 64 + jn * 8 + 2 * t;
            float mk0 = mk[col], mk1 = mk[col + 1];
            accs[jn][0] += mk0; accs[jn][1] += mk1;
            accs[jn][2] += mk0; accs[jn][3] += mk1;
            tmax0 = fmaxf(tmax0, fmaxf(accs[jn][0], accs[jn][1]));
            tmax1 = fmaxf(tmax1, fmaxf(accs[jn][2], accs[jn][3]));
        }
#pragma unroll
        for (int d = 1; d < 4; d <<= 1) {
            tmax0 = fmaxf(tmax0, __shfl_xor_sync(0xffffffffu, tmax0, d));
            tmax1 = fmaxf(tmax1, __shfl_xor_sync(0xffffffffu, tmax1, d));
        }
        float mn0 = fmaxf(m_prev[0], tmax0);
        float mn1 = fmaxf(m_prev[1], tmax1);
        float sc0 = __expf(m_prev[0] - mn0);
        float sc1 = __expf(m_prev[1] - mn1);
        m_prev[0] = mn0; m_prev[1] = mn1;

        float ts0 = 0.f, ts1 = 0.f;
#pragma unroll
        for (int jn = 0; jn < 8; jn++) {
            float p0 = __expf(accs[jn][0] - mn0);
            float p1 = __expf(accs[jn][1] - mn0);
            float p2 = __expf(accs[jn][2] - mn1);
            float p3 = __expf(accs[jn][3] - mn1);
            ts0 += p0 + p1; ts1 += p2 + p3;
            Ps[(wr + g) * PLD + jn * 4 + t] = packh2(p0, p1);
            Ps[(wr + g + 8) * PLD + jn * 4 + t] = packh2(p2, p3);
        }
#pragma unroll
        for (int d = 1; d < 4; d <<= 1) {
            ts0 += __shfl_xor_sync(0xffffffffu, ts0, d);
            ts1 += __shfl_xor_sync(0xffffffffu, ts1, d);
        }
        l_acc[0] = l_acc[0] * sc0 + ts0;
        l_acc[1] = l_acc[1] * sc1 + ts1;
#pragma unroll
        for (int jn = 0; jn < 8; jn++) {
            o[jn][0] *= sc0; o[jn][1] *= sc0;
            o[jn][2] *= sc1; o[jn][3] *= sc1;
        }
        __syncthreads();   // Ps visible to all warps (P frags cross warp rows? no
                           // — but V/K reload next iter needs all reads done)

        // ---- O += P V  (P via ldmatrix, V via ldmatrix.x4.trans) ----
#pragma unroll
        for (int ks = 0; ks < 4; ks++) {   // 4 x k16 over 64 keys
            const uint32_t kb = ks * 8 * 4;
            uint32_t pa[4];
            ldmx4(pa, Psb + poff + kb);
            const uint32_t vrow = Vsb + voff + (uint32_t)(ks * 16 * VLD) * 4;
#pragma unroll
            for (int p = 0; p < 4; p++) {
                uint32_t q[4];
                ldmx4t(q, vrow + p * 32);
                uint32_t b0[2] = {q[0], q[1]};
                uint32_t b1[2] = {q[2], q[3]};
                mma16(o[2 * p], pa, b0);
                mma16(o[2 * p + 1], pa, b1);
            }
        }
    }

    // ---- epilogue: normalize, pack half2 -> g_oh [B*N, CH] ----
    float inv0 = 1.0f / l_acc[0], inv1 = 1.0f / l_acc[1];
    uint32_t* og = g_oh + (size_t)(b * NN + q0 + wr + g) * CH + h * (HD / 2);
#pragma unroll
    for (int jn = 0; jn < 8; jn++) {
        og[jn * 4 + t] = packh2(o[jn][0] * inv0, o[jn][1] * inv0);
        og[(size_t)8 * CH + jn * 4 + t] = packh2(o[jn][2] * inv1, o[jn][3] * inv1);
    }
}

// ---------------------------------------------------------------------------
extern "C" void kernel_launch(void* const* d_in, const int* in_sizes, int n_in,
                              void* d_out, int out_size) {
    const float* x = (const float*)d_in[0];       // [B,N,C]
    const float* mask = (const float*)d_in[1];    // [B,N]
    const float* W_qkv = (const float*)d_in[2];   // [3C,C]
    const float* W_proj = (const float*)d_in[3];  // [C,C]
    const float* b_proj = (const float*)d_in[4];  // [C]
    float* out = (float*)d_out;                   // [B,N,C]

    static bool once = false;
    if (!once) {
        cudaFuncSetAttribute(attn_flash, cudaFuncAttributeMaxDynamicSharedMemorySize,
                             ATTN_SMEM);
        once = true;
    }

    cvt_kernel<0><<<MTOT * CC / 1024, 256>>>(x);
    cvt_kernel<1><<<3 * CC * CC / 1024, 256>>>(W_qkv);
    cvt_kernel<2><<<CC * CC / 1024, 256>>>(W_proj);

    gemm_h<0><<<dim3(3 * CC / 128, MTOT / 128), 128>>>(nullptr, nullptr);
    attn_flash<<<dim3(NN / QT, BB * HH), 256, ATTN_SMEM>>>(mask);
    gemm_h<1><<<dim3(CC / 128, MTOT / 128), 128>>>(b_proj, out);
}